// round 3
// baseline (speedup 1.0000x reference)
#include <cuda_runtime.h>
#include <math.h>

// ---------------- problem constants ----------------
#define N_MAX   50000
#define E_MAX   800000
#define IN_CH   128
#define HIDC    32
#define H1CH    128      // heads1 * hid
#define CATCH   160
#define OUTCH   64
#define NEG_SLOPE 0.2f
#define BN_EPS    1e-5f

// ---------------- device scratch (no allocs allowed) ----------------
__device__ float g_xl1 [N_MAX * H1CH];
__device__ float g_xr1 [N_MAX * H1CH];
__device__ float g_h1  [N_MAX * H1CH];
__device__ float g_h1n [N_MAX * H1CH];
__device__ float g_xlr2[N_MAX * 64];
__device__ float g_h2e [N_MAX * HIDC];
__device__ float g_cat [N_MAX * CATCH];
__device__ float g_w2cat[128 * 64];

__device__ int   g_counts[N_MAX];
__device__ int   g_incl  [N_MAX];
__device__ int   g_rowptr[N_MAX + 1];
__device__ int   g_srcs  [E_MAX];
__device__ int   g_bsums [64];
__device__ int   g_boff  [64];

__device__ float g_sum  [H1CH];
__device__ float g_sumsq[H1CH];
__device__ float g_scale[H1CH];
__device__ float g_shift[H1CH];

// ---------------- helpers ----------------
__device__ __forceinline__ float lrelu(float v) { return v > 0.f ? v : NEG_SLOPE * v; }
__device__ __forceinline__ float eluf(float v)  { return v > 0.f ? v : expm1f(v); }

// ---------------- CSR build ----------------
__global__ void k_zero(int n) {
    int i = blockIdx.x * blockDim.x + threadIdx.x;
    if (i < n) g_counts[i] = 0;
    if (i < H1CH) { g_sum[i] = 0.f; g_sumsq[i] = 0.f; }
}

__global__ void k_count(const int* __restrict__ ei, int e) {
    int i = blockIdx.x * blockDim.x + threadIdx.x;
    if (i < e) {
        int d = ei[e + i];
        atomicAdd(&g_counts[d], 1);
    }
}

__global__ void k_scan1(int n) {
    __shared__ int sh[1024];
    int i = blockIdx.x * 1024 + threadIdx.x;
    int v = (i < n) ? g_counts[i] : 0;
    sh[threadIdx.x] = v;
    __syncthreads();
    for (int off = 1; off < 1024; off <<= 1) {
        int t = (threadIdx.x >= off) ? sh[threadIdx.x - off] : 0;
        __syncthreads();
        sh[threadIdx.x] += t;
        __syncthreads();
    }
    if (i < n) g_incl[i] = sh[threadIdx.x];
    if (threadIdx.x == 1023) g_bsums[blockIdx.x] = sh[1023];
}

__global__ void k_scan2(int nb) {
    if (threadIdx.x == 0) {
        int run = 0;
        for (int b = 0; b < nb; b++) {
            int t = g_bsums[b];
            g_boff[b] = run;
            run += t;
        }
    }
}

__global__ void k_scan3(int n) {
    int i = blockIdx.x * 1024 + threadIdx.x;
    if (i < n) {
        int c = g_counts[i];
        int boff = g_boff[blockIdx.x];
        g_rowptr[i] = g_incl[i] - c + boff;
        g_counts[i] = 0;
        if (i == n - 1) g_rowptr[n] = g_incl[i] + boff;
    }
}

__global__ void k_fill(const int* __restrict__ ei, int e) {
    int i = blockIdx.x * blockDim.x + threadIdx.x;
    if (i < e) {
        int d = ei[e + i];
        int s = ei[i];
        int pos = g_rowptr[d] + atomicAdd(&g_counts[d], 1);
        g_srcs[pos] = s;
    }
}

// ---------------- SGEMM body (register-blocked, fp32) ----------------
// C[M,N] = A[M,K] @ B[K,N] (+ bias[N] if bias != nullptr)
// requires: N % BN == 0, K % BK == 0 (M ragged handled)
template <int BM, int BN, int BK, int TM, int TN>
__device__ __forceinline__ void sgemm_body(const float* __restrict__ A,
                                           const float* __restrict__ B,
                                           float* __restrict__ C,
                                           int M, int N, int K,
                                           const float* __restrict__ bias) {
    constexpr int THREADS = (BM / TM) * (BN / TN);
    __shared__ float As[BK][BM];
    __shared__ float Bs[BK][BN];

    const int tid = threadIdx.x;
    const int rowBase = blockIdx.x * BM;
    const int colBase = blockIdx.y * BN;
    const int tCol = tid % (BN / TN);
    const int tRow = tid / (BN / TN);

    float acc[TM][TN];
#pragma unroll
    for (int m = 0; m < TM; m++)
#pragma unroll
        for (int n = 0; n < TN; n++) acc[m][n] = 0.f;

    constexpr int A_F4 = BM * BK / 4;
    constexpr int B_F4 = BK * BN / 4;

    for (int kt = 0; kt < K; kt += BK) {
#pragma unroll
        for (int it = 0; it < A_F4 / THREADS; it++) {
            int f = tid + it * THREADS;
            int r = f / (BK / 4);
            int kq = f % (BK / 4);
            int grow = rowBase + r;
            float4 v = make_float4(0.f, 0.f, 0.f, 0.f);
            if (grow < M)
                v = *reinterpret_cast<const float4*>(A + (size_t)grow * K + kt + kq * 4);
            As[kq * 4 + 0][r] = v.x;
            As[kq * 4 + 1][r] = v.y;
            As[kq * 4 + 2][r] = v.z;
            As[kq * 4 + 3][r] = v.w;
        }
#pragma unroll
        for (int it = 0; it < B_F4 / THREADS; it++) {
            int f = tid + it * THREADS;
            int kr = f / (BN / 4);
            int c4 = f % (BN / 4);
            float4 v = *reinterpret_cast<const float4*>(B + (size_t)(kt + kr) * N + colBase + c4 * 4);
            *reinterpret_cast<float4*>(&Bs[kr][c4 * 4]) = v;
        }
        __syncthreads();

#pragma unroll
        for (int k = 0; k < BK; k++) {
            float ra[TM], rb[TN];
#pragma unroll
            for (int m = 0; m < TM; m += 4)
                *reinterpret_cast<float4*>(&ra[m]) =
                    *reinterpret_cast<const float4*>(&As[k][tRow * TM + m]);
#pragma unroll
            for (int n = 0; n < TN; n += 4)
                *reinterpret_cast<float4*>(&rb[n]) =
                    *reinterpret_cast<const float4*>(&Bs[k][tCol * TN + n]);
#pragma unroll
            for (int m = 0; m < TM; m++)
#pragma unroll
                for (int n = 0; n < TN; n++) acc[m][n] = fmaf(ra[m], rb[n], acc[m][n]);
        }
        __syncthreads();
    }

    float bv[TN];
#pragma unroll
    for (int n = 0; n < TN; n++)
        bv[n] = bias ? bias[colBase + tCol * TN + n] : 0.f;

#pragma unroll
    for (int m = 0; m < TM; m++) {
        int row = rowBase + tRow * TM + m;
        if (row < M) {
#pragma unroll
            for (int n0 = 0; n0 < TN; n0 += 4) {
                float4 v;
                v.x = acc[m][n0 + 0] + bv[n0 + 0];
                v.y = acc[m][n0 + 1] + bv[n0 + 1];
                v.z = acc[m][n0 + 2] + bv[n0 + 2];
                v.w = acc[m][n0 + 3] + bv[n0 + 3];
                *reinterpret_cast<float4*>(C + (size_t)row * N + colBase + tCol * TN + n0) = v;
            }
        }
    }
}

// Thin wrappers binding __device__ scratch (no host-side symbol addressing).
__global__ void k_gemm_xl1(const float* __restrict__ x, const float* __restrict__ W, int M) {
    sgemm_body<128, 128, 16, 8, 8>(x, W, g_xl1, M, 128, 128, nullptr);
}
__global__ void k_gemm_xr1(const float* __restrict__ x, const float* __restrict__ W, int M) {
    sgemm_body<128, 128, 16, 8, 8>(x, W, g_xr1, M, 128, 128, nullptr);
}
__global__ void k_gemm_xlr2(int M) {
    sgemm_body<128, 64, 16, 8, 4>(g_h1n, g_w2cat, g_xlr2, M, 64, 128, nullptr);
}
__global__ void k_gemm_out(const float* __restrict__ Wc, const float* __restrict__ bc,
                           float* __restrict__ out, int M) {
    sgemm_body<128, 64, 16, 8, 4>(g_cat, Wc, out, M, 64, CATCH, bc);
}

// ---------------- GAT layer 1: warp-per-node, online softmax ----------------
__global__ void k_gat1_agg(const float* __restrict__ att1, const float* __restrict__ b1, int n) {
    int node = blockIdx.x * (blockDim.x >> 5) + (threadIdx.x >> 5);
    if (node >= n) return;
    int lane = threadIdx.x & 31;

    const float4* xl = reinterpret_cast<const float4*>(g_xl1);
    const float4* xr = reinterpret_cast<const float4*>(g_xr1);

    float4 xrv = xr[node * 32 + lane];
    float4 attv = *reinterpret_cast<const float4*>(att1 + (lane >> 3) * HIDC + (lane & 7) * 4);

    // self loop first: weight exp(0)=1 relative to its own logit
    float4 msg = xl[node * 32 + lane];
    float p = lrelu(msg.x + xrv.x) * attv.x + lrelu(msg.y + xrv.y) * attv.y +
              lrelu(msg.z + xrv.z) * attv.z + lrelu(msg.w + xrv.w) * attv.w;
    p += __shfl_xor_sync(0xffffffffu, p, 1);
    p += __shfl_xor_sync(0xffffffffu, p, 2);
    p += __shfl_xor_sync(0xffffffffu, p, 4);

    float m = p;
    float lsum = 1.f;
    float4 acc = msg;

    int beg = g_rowptr[node];
    int end = g_rowptr[node + 1];
    for (int i = beg; i < end; i++) {
        int s = g_srcs[i];
        msg = xl[s * 32 + lane];
        float q = lrelu(msg.x + xrv.x) * attv.x + lrelu(msg.y + xrv.y) * attv.y +
                  lrelu(msg.z + xrv.z) * attv.z + lrelu(msg.w + xrv.w) * attv.w;
        q += __shfl_xor_sync(0xffffffffu, q, 1);
        q += __shfl_xor_sync(0xffffffffu, q, 2);
        q += __shfl_xor_sync(0xffffffffu, q, 4);
        float mn = fmaxf(m, q);
        float sc = __expf(m - mn);
        float w = __expf(q - mn);
        lsum = lsum * sc + w;
        acc.x = acc.x * sc + w * msg.x;
        acc.y = acc.y * sc + w * msg.y;
        acc.z = acc.z * sc + w * msg.z;
        acc.w = acc.w * sc + w * msg.w;
        m = mn;
    }

    float inv = 1.f / lsum;
    float4 bvv = *reinterpret_cast<const float4*>(b1 + lane * 4);
    float4 o;
    o.x = acc.x * inv + bvv.x;
    o.y = acc.y * inv + bvv.y;
    o.z = acc.z * inv + bvv.z;
    o.w = acc.w * inv + bvv.w;
    reinterpret_cast<float4*>(g_h1)[node * 32 + lane] = o;
}

// ---------------- BatchNorm ----------------
__global__ void k_bn_stats(int n) {
    int c = threadIdx.x;  // 128 threads
    float s = 0.f, q = 0.f;
    for (int r = blockIdx.x; r < n; r += gridDim.x) {
        float v = g_h1[(size_t)r * H1CH + c];
        s += v;
        q += v * v;
    }
    atomicAdd(&g_sum[c], s);
    atomicAdd(&g_sumsq[c], q);
}

__global__ void k_bn_final(const float* __restrict__ gamma, const float* __restrict__ beta, int n) {
    int c = threadIdx.x;
    if (c < H1CH) {
        float mu = g_sum[c] / (float)n;
        float var = g_sumsq[c] / (float)n - mu * mu;
        float rs = rsqrtf(var + BN_EPS);
        float sc = rs * gamma[c];
        g_scale[c] = sc;
        g_shift[c] = beta[c] - mu * sc;
    }
}

__global__ void k_bnelu(int total) {
    int i = blockIdx.x * blockDim.x + threadIdx.x;
    if (i < total) {
        int c = i & (H1CH - 1);
        float v = g_h1[i] * g_scale[c] + g_shift[c];
        g_h1n[i] = eluf(v);
    }
}

// ---------------- W2 concat [W2l | W2r] -> [128,64] ----------------
__global__ void k_w2cat(const float* __restrict__ W2l, const float* __restrict__ W2r) {
    int i = blockIdx.x * blockDim.x + threadIdx.x;
    if (i < 128 * 64) {
        int k = i >> 6;
        int j = i & 63;
        g_w2cat[i] = (j < 32) ? W2l[k * 32 + j] : W2r[k * 32 + (j - 32)];
    }
}

// ---------------- GAT layer 2 (1 head, 32 ch) ----------------
__global__ void k_gat2_agg(const float* __restrict__ att2, const float* __restrict__ b2, int n) {
    int node = blockIdx.x * (blockDim.x >> 5) + (threadIdx.x >> 5);
    if (node >= n) return;
    int lane = threadIdx.x & 31;

    float xrc = g_xlr2[node * 64 + 32 + lane];
    float ac = att2[lane];

    float msg = g_xlr2[node * 64 + lane];
    float p = lrelu(msg + xrc) * ac;
#pragma unroll
    for (int off = 16; off >= 1; off >>= 1) p += __shfl_xor_sync(0xffffffffu, p, off);

    float m = p, lsum = 1.f, acc = msg;

    int beg = g_rowptr[node];
    int end = g_rowptr[node + 1];
    for (int i = beg; i < end; i++) {
        int s = g_srcs[i];
        msg = g_xlr2[s * 64 + lane];
        float q = lrelu(msg + xrc) * ac;
#pragma unroll
        for (int off = 16; off >= 1; off >>= 1) q += __shfl_xor_sync(0xffffffffu, q, off);
        float mn = fmaxf(m, q);
        float sc = __expf(m - mn);
        float w = __expf(q - mn);
        lsum = lsum * sc + w;
        acc = acc * sc + w * msg;
        m = mn;
    }
    g_h2e[node * 32 + lane] = eluf(acc / lsum + b2[lane]);
}

// ---------------- concat [elu(h2), x] -> cat[N,160] ----------------
__global__ void k_concat(const float* __restrict__ x, int n) {
    int i = blockIdx.x * blockDim.x + threadIdx.x;
    int total = n * CATCH;
    if (i < total) {
        int row = i / CATCH;
        int c = i - row * CATCH;
        g_cat[i] = (c < 32) ? g_h2e[row * 32 + c] : __ldg(&x[(size_t)row * IN_CH + (c - 32)]);
    }
}

// ---------------- launch ----------------
extern "C" void kernel_launch(void* const* d_in, const int* in_sizes, int n_in,
                              void* d_out, int out_size) {
    const float* x     = (const float*)d_in[0];
    const int*   ei    = (const int*)d_in[1];   // int64 in reference, int32 in practice (JAX x64 off)
    const float* W1l   = (const float*)d_in[2];
    const float* W1r   = (const float*)d_in[3];
    const float* att1  = (const float*)d_in[4];
    const float* b1    = (const float*)d_in[5];
    const float* gamma = (const float*)d_in[6];
    const float* beta  = (const float*)d_in[7];
    const float* W2l   = (const float*)d_in[8];
    const float* W2r   = (const float*)d_in[9];
    const float* att2  = (const float*)d_in[10];
    const float* b2    = (const float*)d_in[11];
    const float* Wc    = (const float*)d_in[12];
    const float* bc    = (const float*)d_in[13];
    float* out = (float*)d_out;

    const int n = in_sizes[0] / IN_CH;   // 50000
    const int e = in_sizes[1] / 2;       // 800000

    const int nb = (n + 1023) / 1024;

    // --- CSR build ---
    k_zero<<<(n + 255) / 256, 256>>>(n);
    k_count<<<(e + 255) / 256, 256>>>(ei, e);
    k_scan1<<<nb, 1024>>>(n);
    k_scan2<<<1, 32>>>(nb);
    k_scan3<<<nb, 1024>>>(n);
    k_fill<<<(e + 255) / 256, 256>>>(ei, e);

    // --- conv1 projections: xl1 = x@W1l, xr1 = x@W1r ---
    dim3 g1((n + 127) / 128, 1);
    k_gemm_xl1<<<g1, 256>>>(x, W1l, n);
    k_gemm_xr1<<<g1, 256>>>(x, W1r, n);

    // --- conv1 edge softmax + aggregate (+b1) ---
    k_gat1_agg<<<(n + 7) / 8, 256>>>(att1, b1, n);

    // --- BN (train-mode batch stats) + ELU ---
    k_bn_stats<<<256, 128>>>(n);
    k_bn_final<<<1, 128>>>(gamma, beta, n);
    k_bnelu<<<(n * H1CH + 255) / 256, 256>>>(n * H1CH);

    // --- conv2 projections (fused l|r): xlr2 = h1n @ [W2l|W2r] ---
    k_w2cat<<<(128 * 64 + 255) / 256, 256>>>(W2l, W2r);
    k_gemm_xlr2<<<g1, 256>>>(n);

    // --- conv2 edge softmax + aggregate, +b2, ELU ---
    k_gat2_agg<<<(n + 7) / 8, 256>>>(att2, b2, n);

    // --- classifier: out = [h2e | x] @ Wc + bc ---
    k_concat<<<(n * CATCH + 255) / 256, 256>>>(x, n);
    k_gemm_out<<<g1, 256>>>(Wc, bc, out, n);
}

// round 4
// speedup vs baseline: 1.4561x; 1.4561x over previous
#include <cuda_runtime.h>
#include <math.h>
#include <stdint.h>

// ---------------- problem constants ----------------
#define N_MAX   50000
#define E_MAX   800000
#define IN_CH   128
#define HIDC    32
#define H1CH    128      // heads1 * hid
#define CATCH   160
#define OUTCH   64
#define NEG_SLOPE 0.2f
#define BN_EPS    1e-5f

// ---------------- device scratch (no allocs allowed) ----------------
__device__ float g_xlr1[N_MAX * 256];   // [xl1 | xr1] interleaved per row
__device__ float g_h1  [N_MAX * H1CH];
__device__ float g_xlr2[N_MAX * 64];
__device__ float g_h2e [N_MAX * HIDC];
__device__ float g_w1cat[128 * 256];
__device__ float g_w2cat[128 * 64];

__device__ int   g_counts[N_MAX];
__device__ int   g_incl  [N_MAX];
__device__ int   g_rowptr[N_MAX + 1];
__device__ int   g_srcs  [E_MAX];
__device__ int   g_bsums [64];
__device__ int   g_boff  [64];

__device__ float g_sum  [H1CH];
__device__ float g_sumsq[H1CH];
__device__ float g_scale[H1CH];
__device__ float g_shift[H1CH];

// ---------------- helpers ----------------
__device__ __forceinline__ float lrelu(float v) { return v > 0.f ? v : NEG_SLOPE * v; }
__device__ __forceinline__ float eluf(float v)  { return v > 0.f ? v : expm1f(v); }

__device__ __forceinline__ uint32_t f2tf32(float f) {
    uint32_t u;
    asm("cvt.rna.tf32.f32 %0, %1;" : "=r"(u) : "f"(f));
    return u;
}

__device__ __forceinline__ void mma_m16n8k8(float* c, const uint32_t* a, const uint32_t* b) {
    asm volatile(
        "mma.sync.aligned.m16n8k8.row.col.f32.tf32.tf32.f32 "
        "{%0,%1,%2,%3}, {%4,%5,%6,%7}, {%8,%9}, {%0,%1,%2,%3};\n"
        : "+f"(c[0]), "+f"(c[1]), "+f"(c[2]), "+f"(c[3])
        : "r"(a[0]), "r"(a[1]), "r"(a[2]), "r"(a[3]), "r"(b[0]), "r"(b[1]));
}

// ---------------- CSR build ----------------
__global__ void k_zero(int n) {
    int i = blockIdx.x * blockDim.x + threadIdx.x;
    if (i < n) g_counts[i] = 0;
    if (i < H1CH) { g_sum[i] = 0.f; g_sumsq[i] = 0.f; }
}

__global__ void k_count(const int* __restrict__ ei, int e) {
    int i = blockIdx.x * blockDim.x + threadIdx.x;
    if (i < e) atomicAdd(&g_counts[ei[e + i]], 1);
}

__global__ void k_scan1(int n) {
    __shared__ int sh[1024];
    int i = blockIdx.x * 1024 + threadIdx.x;
    int v = (i < n) ? g_counts[i] : 0;
    sh[threadIdx.x] = v;
    __syncthreads();
    for (int off = 1; off < 1024; off <<= 1) {
        int t = (threadIdx.x >= off) ? sh[threadIdx.x - off] : 0;
        __syncthreads();
        sh[threadIdx.x] += t;
        __syncthreads();
    }
    if (i < n) g_incl[i] = sh[threadIdx.x];
    if (threadIdx.x == 1023) g_bsums[blockIdx.x] = sh[1023];
}

__global__ void k_scan2(int nb) {
    int t = threadIdx.x;               // 64 threads
    int v = (t < nb) ? g_bsums[t] : 0;
    int lane = t & 31, w = t >> 5;
    int s = v;
#pragma unroll
    for (int off = 1; off < 32; off <<= 1) {
        int u = __shfl_up_sync(0xffffffffu, s, off);
        if (lane >= off) s += u;
    }
    __shared__ int wtot;
    if (w == 0 && lane == 31) wtot = s;
    __syncthreads();
    int base = (w == 1) ? wtot : 0;
    if (t < nb) g_boff[t] = base + s - v;   // exclusive prefix
}

__global__ void k_scan3(int n) {
    int i = blockIdx.x * 1024 + threadIdx.x;
    if (i < n) {
        int c = g_counts[i];
        int boff = g_boff[blockIdx.x];
        g_rowptr[i] = g_incl[i] - c + boff;
        g_counts[i] = 0;
        if (i == n - 1) g_rowptr[n] = g_incl[i] + boff;
    }
}

__global__ void k_fill(const int* __restrict__ ei, int e) {
    int i = blockIdx.x * blockDim.x + threadIdx.x;
    if (i < e) {
        int d = ei[e + i];
        int s = ei[i];
        int pos = g_rowptr[d] + atomicAdd(&g_counts[d], 1);
        g_srcs[pos] = s;
    }
}

// ---------------- weight concat kernels ----------------
__global__ void k_w1cat(const float* __restrict__ W1l, const float* __restrict__ W1r) {
    int i = blockIdx.x * blockDim.x + threadIdx.x;
    if (i < 128 * 256) {
        int k = i >> 8, j = i & 255;
        g_w1cat[i] = (j < 128) ? W1l[k * 128 + j] : W1r[k * 128 + j - 128];
    }
}

__global__ void k_w2cat(const float* __restrict__ W2l, const float* __restrict__ W2r) {
    int i = blockIdx.x * blockDim.x + threadIdx.x;
    if (i < 128 * 64) {
        int k = i >> 6, j = i & 63;
        g_w2cat[i] = (j < 32) ? W2l[k * 32 + j] : W2r[k * 32 + (j - 32)];
    }
}

// ---------------- tf32 MMA GEMM ----------------
// C[M,N] = A[M,K] @ B[K,N] (+bias). BK=32 fixed. 256 threads.
// MODE 0: A = plain pointer
// MODE 1: A = elu(bn(g_h1))   (K=128)
// MODE 2: A = [g_h2e | xcat]  (K=160; tile0 from h2e, rest from xcat)
template <int BM, int BN, int WM_CNT, int WN_CNT, int MODE>
__device__ __forceinline__ void mma_gemm_body(
    const float* __restrict__ A, const float* __restrict__ B,
    float* __restrict__ C, int M, int K, int ldb, int ldc,
    const float* __restrict__ bias, const float* __restrict__ xcat)
{
    constexpr int BK = 32;
    constexpr int THREADS = WM_CNT * WN_CNT * 32;
    constexpr int WM = BM / WM_CNT;
    constexpr int WN = BN / WN_CNT;
    constexpr int MT = WM / 16;
    constexpr int NT = WN / 8;
    constexpr int LDA = BK + 4;   // 36 floats: conflict-free frag loads, 16B-aligned rows
    constexpr int LDB = BN + 8;

    __shared__ float As[BM][LDA];
    __shared__ float Bs[BK][LDB];

    const int tid = threadIdx.x;
    const int wid = tid >> 5;
    const int lane = tid & 31;
    const int warpM = wid / WN_CNT;
    const int warpN = wid % WN_CNT;
    const int g = lane >> 2;     // groupID
    const int tg = lane & 3;     // threadID_in_group

    const int rowBase = blockIdx.x * BM;
    const int colBase = blockIdx.y * BN;

    float acc[MT][NT][4];
#pragma unroll
    for (int mt = 0; mt < MT; mt++)
#pragma unroll
        for (int nt = 0; nt < NT; nt++)
#pragma unroll
            for (int i = 0; i < 4; i++) acc[mt][nt][i] = 0.f;

    for (int kt = 0; kt < K; kt += BK) {
        // ---- load A tile: BM x BK ----
        constexpr int A_F4 = BM * BK / 4;
#pragma unroll
        for (int it = 0; it < A_F4 / THREADS; it++) {
            int f = tid + it * THREADS;
            int r = f >> 3;              // 8 float4 per row
            int kq = (f & 7) << 2;
            int grow = rowBase + r;
            float4 v = make_float4(0.f, 0.f, 0.f, 0.f);
            if (grow < M) {
                if (MODE == 0) {
                    v = *reinterpret_cast<const float4*>(A + (size_t)grow * K + kt + kq);
                } else if (MODE == 1) {
                    v = *reinterpret_cast<const float4*>(&g_h1[(size_t)grow * 128 + kt + kq]);
                    int c = kt + kq;
                    v.x = eluf(fmaf(v.x, g_scale[c + 0], g_shift[c + 0]));
                    v.y = eluf(fmaf(v.y, g_scale[c + 1], g_shift[c + 1]));
                    v.z = eluf(fmaf(v.z, g_scale[c + 2], g_shift[c + 2]));
                    v.w = eluf(fmaf(v.w, g_scale[c + 3], g_shift[c + 3]));
                } else {
                    if (kt == 0)
                        v = *reinterpret_cast<const float4*>(&g_h2e[(size_t)grow * 32 + kq]);
                    else
                        v = *reinterpret_cast<const float4*>(&xcat[(size_t)grow * 128 + kt - 32 + kq]);
                }
            }
            *reinterpret_cast<float4*>(&As[r][kq]) = v;
        }
        // ---- load B tile: BK x BN ----
        constexpr int B_F4 = BK * BN / 4;
#pragma unroll
        for (int it = 0; it < B_F4 / THREADS; it++) {
            int f = tid + it * THREADS;
            int kr = f / (BN / 4);
            int nq = (f % (BN / 4)) << 2;
            float4 v = *reinterpret_cast<const float4*>(B + (size_t)(kt + kr) * ldb + colBase + nq);
            *reinterpret_cast<float4*>(&Bs[kr][nq]) = v;
        }
        __syncthreads();

#pragma unroll
        for (int kk = 0; kk < BK; kk += 8) {
            uint32_t af[MT][4];
#pragma unroll
            for (int mt = 0; mt < MT; mt++) {
                int m = warpM * WM + mt * 16;
                af[mt][0] = f2tf32(As[m + g][kk + tg]);
                af[mt][1] = f2tf32(As[m + g + 8][kk + tg]);
                af[mt][2] = f2tf32(As[m + g][kk + tg + 4]);
                af[mt][3] = f2tf32(As[m + g + 8][kk + tg + 4]);
            }
            uint32_t bf[NT][2];
#pragma unroll
            for (int nt = 0; nt < NT; nt++) {
                int nn = warpN * WN + nt * 8;
                bf[nt][0] = f2tf32(Bs[kk + tg][nn + g]);
                bf[nt][1] = f2tf32(Bs[kk + tg + 4][nn + g]);
            }
#pragma unroll
            for (int mt = 0; mt < MT; mt++)
#pragma unroll
                for (int nt = 0; nt < NT; nt++)
                    mma_m16n8k8(acc[mt][nt], af[mt], bf[nt]);
        }
        __syncthreads();
    }

    // ---- epilogue ----
#pragma unroll
    for (int mt = 0; mt < MT; mt++) {
        int m0 = rowBase + warpM * WM + mt * 16 + g;
        int m1 = m0 + 8;
#pragma unroll
        for (int nt = 0; nt < NT; nt++) {
            int c0 = colBase + warpN * WN + nt * 8 + 2 * tg;
            float bx = 0.f, by = 0.f;
            if (bias) { bx = bias[c0]; by = bias[c0 + 1]; }
            if (m0 < M) {
                float2 v = make_float2(acc[mt][nt][0] + bx, acc[mt][nt][1] + by);
                *reinterpret_cast<float2*>(&C[(size_t)m0 * ldc + c0]) = v;
            }
            if (m1 < M) {
                float2 v = make_float2(acc[mt][nt][2] + bx, acc[mt][nt][3] + by);
                *reinterpret_cast<float2*>(&C[(size_t)m1 * ldc + c0]) = v;
            }
        }
    }
}

__global__ void __launch_bounds__(256) k_gemm1(const float* __restrict__ x, int M) {
    mma_gemm_body<128, 128, 2, 4, 0>(x, g_w1cat, g_xlr1, M, 128, 256, 256, nullptr, nullptr);
}
__global__ void __launch_bounds__(256) k_gemm2(int M) {
    mma_gemm_body<128, 64, 4, 2, 1>(nullptr, g_w2cat, g_xlr2, M, 128, 64, 64, nullptr, nullptr);
}
__global__ void __launch_bounds__(256) k_gemm3(const float* __restrict__ Wc,
                                               const float* __restrict__ bc,
                                               const float* __restrict__ x,
                                               float* __restrict__ out, int M) {
    mma_gemm_body<128, 64, 4, 2, 2>(nullptr, Wc, out, M, 160, 64, 64, bc, x);
}

// ---------------- GAT layer 1: warp-per-node, online softmax ----------------
__global__ void k_gat1_agg(const float* __restrict__ att1, const float* __restrict__ b1, int n) {
    int node = blockIdx.x * (blockDim.x >> 5) + (threadIdx.x >> 5);
    if (node >= n) return;
    int lane = threadIdx.x & 31;

    const float4* xlr = reinterpret_cast<const float4*>(g_xlr1);  // row = 64 float4: [xl(32) | xr(32)]

    float4 xrv = xlr[node * 64 + 32 + lane];
    float4 attv = *reinterpret_cast<const float4*>(att1 + (lane >> 3) * HIDC + (lane & 7) * 4);

    // self loop first
    float4 msg = xlr[node * 64 + lane];
    float p = lrelu(msg.x + xrv.x) * attv.x + lrelu(msg.y + xrv.y) * attv.y +
              lrelu(msg.z + xrv.z) * attv.z + lrelu(msg.w + xrv.w) * attv.w;
    p += __shfl_xor_sync(0xffffffffu, p, 1);
    p += __shfl_xor_sync(0xffffffffu, p, 2);
    p += __shfl_xor_sync(0xffffffffu, p, 4);

    float m = p;
    float lsum = 1.f;
    float4 acc = msg;

    int beg = g_rowptr[node];
    int end = g_rowptr[node + 1];
    for (int i = beg; i < end; i++) {
        int s = g_srcs[i];
        msg = xlr[s * 64 + lane];
        float q = lrelu(msg.x + xrv.x) * attv.x + lrelu(msg.y + xrv.y) * attv.y +
                  lrelu(msg.z + xrv.z) * attv.z + lrelu(msg.w + xrv.w) * attv.w;
        q += __shfl_xor_sync(0xffffffffu, q, 1);
        q += __shfl_xor_sync(0xffffffffu, q, 2);
        q += __shfl_xor_sync(0xffffffffu, q, 4);
        float mn = fmaxf(m, q);
        float sc = __expf(m - mn);
        float w = __expf(q - mn);
        lsum = lsum * sc + w;
        acc.x = acc.x * sc + w * msg.x;
        acc.y = acc.y * sc + w * msg.y;
        acc.z = acc.z * sc + w * msg.z;
        acc.w = acc.w * sc + w * msg.w;
        m = mn;
    }

    float inv = 1.f / lsum;
    float4 bvv = *reinterpret_cast<const float4*>(b1 + lane * 4);
    float4 o;
    o.x = acc.x * inv + bvv.x;
    o.y = acc.y * inv + bvv.y;
    o.z = acc.z * inv + bvv.z;
    o.w = acc.w * inv + bvv.w;
    reinterpret_cast<float4*>(g_h1)[node * 32 + lane] = o;
}

// ---------------- BatchNorm ----------------
__global__ void k_bn_stats(int n) {
    int c = threadIdx.x;  // 128 threads
    float s = 0.f, q = 0.f;
    for (int r = blockIdx.x; r < n; r += gridDim.x) {
        float v = g_h1[(size_t)r * H1CH + c];
        s += v;
        q += v * v;
    }
    atomicAdd(&g_sum[c], s);
    atomicAdd(&g_sumsq[c], q);
}

__global__ void k_bn_final(const float* __restrict__ gamma, const float* __restrict__ beta, int n) {
    int c = threadIdx.x;
    if (c < H1CH) {
        float mu = g_sum[c] / (float)n;
        float var = g_sumsq[c] / (float)n - mu * mu;
        float rs = rsqrtf(var + BN_EPS);
        float sc = rs * gamma[c];
        g_scale[c] = sc;
        g_shift[c] = beta[c] - mu * sc;
    }
}

// ---------------- GAT layer 2 (1 head, 32 ch) ----------------
__global__ void k_gat2_agg(const float* __restrict__ att2, const float* __restrict__ b2, int n) {
    int node = blockIdx.x * (blockDim.x >> 5) + (threadIdx.x >> 5);
    if (node >= n) return;
    int lane = threadIdx.x & 31;

    float xrc = g_xlr2[node * 64 + 32 + lane];
    float ac = att2[lane];

    float msg = g_xlr2[node * 64 + lane];
    float p = lrelu(msg + xrc) * ac;
#pragma unroll
    for (int off = 16; off >= 1; off >>= 1) p += __shfl_xor_sync(0xffffffffu, p, off);

    float m = p, lsum = 1.f, acc = msg;

    int beg = g_rowptr[node];
    int end = g_rowptr[node + 1];
    for (int i = beg; i < end; i++) {
        int s = g_srcs[i];
        msg = g_xlr2[s * 64 + lane];
        float q = lrelu(msg + xrc) * ac;
#pragma unroll
        for (int off = 16; off >= 1; off >>= 1) q += __shfl_xor_sync(0xffffffffu, q, off);
        float mn = fmaxf(m, q);
        float sc = __expf(m - mn);
        float w = __expf(q - mn);
        lsum = lsum * sc + w;
        acc = acc * sc + w * msg;
        m = mn;
    }
    g_h2e[node * 32 + lane] = eluf(acc / lsum + b2[lane]);
}

// ---------------- launch ----------------
extern "C" void kernel_launch(void* const* d_in, const int* in_sizes, int n_in,
                              void* d_out, int out_size) {
    const float* x     = (const float*)d_in[0];
    const int*   ei    = (const int*)d_in[1];   // int32 in practice (JAX x64 off)
    const float* W1l   = (const float*)d_in[2];
    const float* W1r   = (const float*)d_in[3];
    const float* att1  = (const float*)d_in[4];
    const float* b1    = (const float*)d_in[5];
    const float* gamma = (const float*)d_in[6];
    const float* beta  = (const float*)d_in[7];
    const float* W2l   = (const float*)d_in[8];
    const float* W2r   = (const float*)d_in[9];
    const float* att2  = (const float*)d_in[10];
    const float* b2    = (const float*)d_in[11];
    const float* Wc    = (const float*)d_in[12];
    const float* bc    = (const float*)d_in[13];
    float* out = (float*)d_out;

    const int n = in_sizes[0] / IN_CH;   // 50000
    const int e = in_sizes[1] / 2;       // 800000
    const int nb = (n + 1023) / 1024;

    // --- weight prep + CSR build ---
    k_w1cat<<<(128 * 256 + 255) / 256, 256>>>(W1l, W1r);
    k_w2cat<<<(128 * 64 + 255) / 256, 256>>>(W2l, W2r);
    k_zero<<<(n + 255) / 256, 256>>>(n);
    k_count<<<(e + 255) / 256, 256>>>(ei, e);
    k_scan1<<<nb, 1024>>>(n);
    k_scan2<<<1, 64>>>(nb);
    k_scan3<<<nb, 1024>>>(n);
    k_fill<<<(e + 255) / 256, 256>>>(ei, e);

    // --- conv1 projection (fused l|r): xlr1 = x @ [W1l|W1r] ---
    dim3 g1((n + 127) / 128, 2);
    k_gemm1<<<g1, 256>>>(x, n);

    // --- conv1 edge softmax + aggregate (+b1) ---
    k_gat1_agg<<<(n + 7) / 8, 256>>>(att1, b1, n);

    // --- BN stats (applied inline in gemm2's A load) ---
    k_bn_stats<<<256, 128>>>(n);
    k_bn_final<<<1, 128>>>(gamma, beta, n);

    // --- conv2 projection: xlr2 = elu(bn(h1)) @ [W2l|W2r] ---
    dim3 g2((n + 127) / 128, 1);
    k_gemm2<<<g2, 256>>>(n);

    // --- conv2 edge softmax + aggregate, +b2, ELU ---
    k_gat2_agg<<<(n + 7) / 8, 256>>>(att2, b2, n);

    // --- classifier: out = [h2e | x] @ Wc + bc ---
    k_gemm3<<<g2, 256>>>(Wc, bc, x, out, n);
}